// round 2
// baseline (speedup 1.0000x reference)
#include <cuda_runtime.h>

// Problem constants
#define A_  4
#define B_  4
#define S_  2048
#define H_  1024
#define NH_ 16
#define HD_ 64
#define BS_ (B_ * S_)     // 8192
#define M1_ (BS_ * A_)    // 32768

// ---------------------------------------------------------------------------
// Scratch (device globals — no allocations allowed in kernel_launch)
// ---------------------------------------------------------------------------
__device__ float g_Q[M1_ * H_];       // 128 MB
__device__ float g_K[M1_ * H_];       // 128 MB
__device__ float g_V[M1_ * H_];       // 128 MB
__device__ float g_pool[BS_ * H_];    // 32 MB
__device__ float g_fused[BS_ * H_];   // 32 MB

// ---------------------------------------------------------------------------
// GEMM: C[m,n] = sum_k A[m,k] * W[k,n] + bias[n] (+ residual)
// Tile 128x128, BK=16, 256 threads, 8x8 per thread, double-buffered smem.
// MODE 0/1/2: A = adapter_outputs with permuted row bases (x = stack+reshape),
//             C = g_Q / g_K / g_V.
// MODE 3:     A = g_pool (natural rows), C = g_fused, epilogue adds residual.
// ---------------------------------------------------------------------------
template <int MODE>
__global__ __launch_bounds__(256, 2)
void gemm_bias(const float* __restrict__ Ain,
               const float* __restrict__ W,
               const float* __restrict__ bias,
               const float* __restrict__ resid)
{
    const int N = H_;
    __shared__ float As[2][16][132];   // [k][m], pad 4
    __shared__ float Bs[2][16][128];   // [k][n]

    const float* A = (MODE == 3) ? (const float*)g_pool : Ain;
    float* C = (MODE == 0) ? g_Q : (MODE == 1) ? g_K : (MODE == 2) ? g_V : g_fused;

    const int t  = threadIdx.x;
    const int nt = blockIdx.x;   // n tile (8)
    const int mt = blockIdx.y;   // m tile

    // A-tile loads: thread t loads row (t>>1), k-cols (t&1)*8 + {0..7}
    const int arow = t >> 1;
    const int acol = (t & 1) * 8;
    const int gm_ld = mt * 128 + arow;
    int abase;
    if (MODE < 3) {
        const int a  = gm_ld & 3;
        const int bs = gm_ld >> 2;
        const int b  = bs >> 11;          // bs / S_
        const int s  = bs & (S_ - 1);
        abase = (((a * B_ + b) * S_) + s) * H_;
    } else {
        abase = gm_ld * H_;
    }
    const float* Ap = A + abase + acol;

    // B-tile loads: thread t loads k-row (t>>4), n-cols (t&15)*8 + {0..7}
    const int brow = t >> 4;
    const int bcol = (t & 15) * 8;
    const float* Bp = W + brow * N + nt * 128 + bcol;

    const int ty = t >> 4;   // 0..15 (m direction)
    const int tx = t & 15;   // 0..15 (n direction)

    // Prologue: load tile 0
    float4 pa0 = *(const float4*)(Ap);
    float4 pa1 = *(const float4*)(Ap + 4);
    float4 pb0 = *(const float4*)(Bp);
    float4 pb1 = *(const float4*)(Bp + 4);

    As[0][acol + 0][arow] = pa0.x;
    As[0][acol + 1][arow] = pa0.y;
    As[0][acol + 2][arow] = pa0.z;
    As[0][acol + 3][arow] = pa0.w;
    As[0][acol + 4][arow] = pa1.x;
    As[0][acol + 5][arow] = pa1.y;
    As[0][acol + 6][arow] = pa1.z;
    As[0][acol + 7][arow] = pa1.w;
    *(float4*)&Bs[0][brow][bcol]     = pb0;
    *(float4*)&Bs[0][brow][bcol + 4] = pb1;
    __syncthreads();

    float acc[8][8];
#pragma unroll
    for (int i = 0; i < 8; i++)
#pragma unroll
        for (int j = 0; j < 8; j++) acc[i][j] = 0.0f;

    const int NK = H_ / 16;   // 64
    for (int kt = 0; kt < NK; kt++) {
        const int cur = kt & 1;
        if (kt + 1 < NK) {
            const float* ap = Ap + (kt + 1) * 16;
            pa0 = *(const float4*)(ap);
            pa1 = *(const float4*)(ap + 4);
            const float* bp = Bp + (kt + 1) * 16 * N;
            pb0 = *(const float4*)(bp);
            pb1 = *(const float4*)(bp + 4);
        }
#pragma unroll
        for (int k = 0; k < 16; k++) {
            const float4 a0 = *(const float4*)&As[cur][k][ty * 8];
            const float4 a1 = *(const float4*)&As[cur][k][ty * 8 + 4];
            const float4 b0 = *(const float4*)&Bs[cur][k][tx * 8];
            const float4 b1 = *(const float4*)&Bs[cur][k][tx * 8 + 4];
            const float af[8]  = {a0.x, a0.y, a0.z, a0.w, a1.x, a1.y, a1.z, a1.w};
            const float bfv[8] = {b0.x, b0.y, b0.z, b0.w, b1.x, b1.y, b1.z, b1.w};
#pragma unroll
            for (int i = 0; i < 8; i++)
#pragma unroll
                for (int j = 0; j < 8; j++)
                    acc[i][j] = fmaf(af[i], bfv[j], acc[i][j]);
        }
        if (kt + 1 < NK) {
            const int nxt = cur ^ 1;
            As[nxt][acol + 0][arow] = pa0.x;
            As[nxt][acol + 1][arow] = pa0.y;
            As[nxt][acol + 2][arow] = pa0.z;
            As[nxt][acol + 3][arow] = pa0.w;
            As[nxt][acol + 4][arow] = pa1.x;
            As[nxt][acol + 5][arow] = pa1.y;
            As[nxt][acol + 6][arow] = pa1.z;
            As[nxt][acol + 7][arow] = pa1.w;
            *(float4*)&Bs[nxt][brow][bcol]     = pb0;
            *(float4*)&Bs[nxt][brow][bcol + 4] = pb1;
            __syncthreads();
        }
    }

    // Epilogue: bias (+ residual), vectorized stores
    const int gn = nt * 128 + tx * 8;
    const float4 bi0 = *(const float4*)(bias + gn);
    const float4 bi1 = *(const float4*)(bias + gn + 4);
#pragma unroll
    for (int i = 0; i < 8; i++) {
        const int m = mt * 128 + ty * 8 + i;
        float4 r0, r1;
        r0.x = acc[i][0] + bi0.x; r0.y = acc[i][1] + bi0.y;
        r0.z = acc[i][2] + bi0.z; r0.w = acc[i][3] + bi0.w;
        r1.x = acc[i][4] + bi1.x; r1.y = acc[i][5] + bi1.y;
        r1.z = acc[i][6] + bi1.z; r1.w = acc[i][7] + bi1.w;
        if (MODE == 3) {
            const float4 rs0 = *(const float4*)(resid + m * H_ + gn);
            const float4 rs1 = *(const float4*)(resid + m * H_ + gn + 4);
            r0.x += rs0.x; r0.y += rs0.y; r0.z += rs0.z; r0.w += rs0.w;
            r1.x += rs1.x; r1.y += rs1.y; r1.z += rs1.z; r1.w += rs1.w;
        }
        float* cp = C + m * N + gn;
        *(float4*)(cp)     = r0;
        *(float4*)(cp + 4) = r1;
    }
}

// ---------------------------------------------------------------------------
// Attention over the adapter axis + mean pool.
// One warp per (bs, head). pooled = (colsum(softmax(QK^T/8))/4) . V
// ---------------------------------------------------------------------------
__global__ __launch_bounds__(256)
void attn_pool_kernel()
{
    const int warp = threadIdx.x >> 5;
    const int lane = threadIdx.x & 31;
    const int unit = blockIdx.x * 8 + warp;   // 0 .. BS_*NH_-1
    const int bs = unit >> 4;
    const int h  = unit & 15;

    const int base = (bs * A_) * H_ + h * HD_;
    float q[A_][2], k[A_][2], v[A_][2];
#pragma unroll
    for (int a = 0; a < A_; a++) {
        const float* qp = g_Q + base + a * H_;
        const float* kp = g_K + base + a * H_;
        const float* vp = g_V + base + a * H_;
        q[a][0] = qp[lane]; q[a][1] = qp[lane + 32];
        k[a][0] = kp[lane]; k[a][1] = kp[lane + 32];
        v[a][0] = vp[lane]; v[a][1] = vp[lane + 32];
    }

    float sc[A_][A_];
#pragma unroll
    for (int i = 0; i < A_; i++)
#pragma unroll
        for (int j = 0; j < A_; j++)
            sc[i][j] = q[i][0] * k[j][0] + q[i][1] * k[j][1];

#pragma unroll
    for (int off = 16; off > 0; off >>= 1)
#pragma unroll
        for (int i = 0; i < A_; i++)
#pragma unroll
            for (int j = 0; j < A_; j++)
                sc[i][j] += __shfl_xor_sync(0xffffffffu, sc[i][j], off);

    // softmax per row (scale = 1/(sqrt(64)*TEMP) = 0.125), accumulate col sums
    float colw[A_] = {0.f, 0.f, 0.f, 0.f};
#pragma unroll
    for (int i = 0; i < A_; i++) {
        float s0 = sc[i][0] * 0.125f, s1 = sc[i][1] * 0.125f;
        float s2 = sc[i][2] * 0.125f, s3 = sc[i][3] * 0.125f;
        const float mx = fmaxf(fmaxf(s0, s1), fmaxf(s2, s3));
        const float e0 = __expf(s0 - mx), e1 = __expf(s1 - mx);
        const float e2 = __expf(s2 - mx), e3 = __expf(s3 - mx);
        const float inv = 1.0f / (e0 + e1 + e2 + e3);
        colw[0] += e0 * inv; colw[1] += e1 * inv;
        colw[2] += e2 * inv; colw[3] += e3 * inv;
    }

    float o0 = 0.f, o1 = 0.f;
#pragma unroll
    for (int j = 0; j < A_; j++) {
        const float c = colw[j] * 0.25f;   // mean over 4 adapters
        o0 = fmaf(c, v[j][0], o0);
        o1 = fmaf(c, v[j][1], o1);
    }
    float* op = g_pool + bs * H_ + h * HD_;
    op[lane]      = o0;
    op[lane + 32] = o1;
}

// ---------------------------------------------------------------------------
// LayerNorm over H=1024 per row. One 256-thread block per row, 4 elems/thread.
// ---------------------------------------------------------------------------
__global__ __launch_bounds__(256)
void ln_kernel(const float* __restrict__ gamma,
               const float* __restrict__ beta,
               float* __restrict__ out)
{
    const int row = blockIdx.x;
    const int t = threadIdx.x;

    const float4 x = ((const float4*)(g_fused + row * H_))[t];
    float s  = x.x + x.y + x.z + x.w;
    float ss = x.x * x.x + x.y * x.y + x.z * x.z + x.w * x.w;
#pragma unroll
    for (int off = 16; off > 0; off >>= 1) {
        s  += __shfl_xor_sync(0xffffffffu, s,  off);
        ss += __shfl_xor_sync(0xffffffffu, ss, off);
    }
    __shared__ float sh_s[8], sh_ss[8];
    if ((t & 31) == 0) { sh_s[t >> 5] = s; sh_ss[t >> 5] = ss; }
    __syncthreads();
    float tot = 0.f, tot2 = 0.f;
#pragma unroll
    for (int w = 0; w < 8; w++) { tot += sh_s[w]; tot2 += sh_ss[w]; }

    const float mu   = tot * (1.0f / H_);
    const float var  = tot2 * (1.0f / H_) - mu * mu;
    const float rstd = rsqrtf(var + 1e-5f);

    const float4 g = ((const float4*)gamma)[t];
    const float4 b = ((const float4*)beta)[t];
    float4 y;
    y.x = (x.x - mu) * rstd * g.x + b.x;
    y.y = (x.y - mu) * rstd * g.y + b.y;
    y.z = (x.z - mu) * rstd * g.z + b.z;
    y.w = (x.w - mu) * rstd * g.w + b.w;
    ((float4*)(out + row * H_))[t] = y;
}

// ---------------------------------------------------------------------------
// Launch
// ---------------------------------------------------------------------------
extern "C" void kernel_launch(void* const* d_in, const int* in_sizes, int n_in,
                              void* d_out, int out_size)
{
    (void)in_sizes; (void)n_in; (void)out_size;
    const float* adapter = (const float*)d_in[0];
    const float* Wq = (const float*)d_in[1];
    const float* bq = (const float*)d_in[2];
    const float* Wk = (const float*)d_in[3];
    const float* bk = (const float*)d_in[4];
    const float* Wv = (const float*)d_in[5];
    const float* bv = (const float*)d_in[6];
    const float* Wo = (const float*)d_in[7];
    const float* bo = (const float*)d_in[8];
    const float* gamma = (const float*)d_in[9];
    const float* beta  = (const float*)d_in[10];
    float* out = (float*)d_out;

    const dim3 blk(256);
    const dim3 grid_qkv(H_ / 128, M1_ / 128);   // (8, 256)
    const dim3 grid_o(H_ / 128, BS_ / 128);     // (8, 64)

    gemm_bias<0><<<grid_qkv, blk>>>(adapter, Wq, bq, nullptr);
    gemm_bias<1><<<grid_qkv, blk>>>(adapter, Wk, bk, nullptr);
    gemm_bias<2><<<grid_qkv, blk>>>(adapter, Wv, bv, nullptr);
    attn_pool_kernel<<<(BS_ * NH_) / 8, blk>>>();
    gemm_bias<3><<<grid_o, blk>>>(nullptr, Wo, bo, adapter);
    ln_kernel<<<BS_, blk>>>(gamma, beta, out);
}

// round 4
// speedup vs baseline: 2.8777x; 2.8777x over previous
#include <cuda_runtime.h>
#include <cuda_bf16.h>
#include <cstdint>

#define A_  4
#define B_  4
#define S_  2048
#define H_  1024
#define NH_ 16
#define HD_ 64
#define BS_ (B_ * S_)     // 8192
#define M1_ (BS_ * A_)    // 32768

// ---------------------------------------------------------------------------
// Scratch (device globals)
// ---------------------------------------------------------------------------
__device__ __align__(256) __nv_bfloat16 g_xhi[M1_ * H_];    // 64 MB
__device__ __align__(256) __nv_bfloat16 g_xlo[M1_ * H_];    // 64 MB
__device__ __align__(256) __nv_bfloat16 g_wThi[4][H_ * H_]; // 8 MB  ([n][k])
__device__ __align__(256) __nv_bfloat16 g_wTlo[4][H_ * H_]; // 8 MB
__device__ __align__(256) float g_Q[M1_ * H_];              // 128 MB
__device__ __align__(256) float g_K[M1_ * H_];              // 128 MB
__device__ __align__(256) float g_V[M1_ * H_];              // 128 MB
__device__ __align__(256) __nv_bfloat16 g_phi[BS_ * H_];    // 16 MB
__device__ __align__(256) __nv_bfloat16 g_plo[BS_ * H_];    // 16 MB
__device__ __align__(256) float g_fused[BS_ * H_];          // 32 MB

// ---------------------------------------------------------------------------
// PTX helpers (all sm_80+ / base-target legal; NO tcgen05)
// ---------------------------------------------------------------------------
__device__ __forceinline__ uint32_t smem_u32(const void* p) {
    uint32_t a;
    asm("{ .reg .u64 t; cvta.to.shared.u64 t, %1; cvt.u32.u64 %0, t; }" : "=r"(a) : "l"(p));
    return a;
}
__device__ __forceinline__ void cp16(uint32_t s, const void* g) {
    asm volatile("cp.async.cg.shared.global [%0], [%1], 16;" :: "r"(s), "l"(g));
}
__device__ __forceinline__ void cp_commit() {
    asm volatile("cp.async.commit_group;" ::: "memory");
}

#define LDM4(d, addr) \
    asm volatile("ldmatrix.sync.aligned.m8n8.x4.shared.b16 {%0,%1,%2,%3}, [%4];" \
                 : "=r"((d)[0]), "=r"((d)[1]), "=r"((d)[2]), "=r"((d)[3]) : "r"(addr))

#define MMA16816(d, a, b0v, b1v) \
    asm volatile("mma.sync.aligned.m16n8k16.row.col.f32.bf16.bf16.f32 " \
                 "{%0,%1,%2,%3}, {%4,%5,%6,%7}, {%8,%9}, {%0,%1,%2,%3};" \
                 : "+f"((d)[0]), "+f"((d)[1]), "+f"((d)[2]), "+f"((d)[3]) \
                 : "r"((a)[0]), "r"((a)[1]), "r"((a)[2]), "r"((a)[3]), \
                   "r"(b0v), "r"(b1v))

// ---------------------------------------------------------------------------
// Conversion kernels
// ---------------------------------------------------------------------------
__global__ __launch_bounds__(256) void conv_x(const float* __restrict__ ad)
{
    const int m = blockIdx.x;
    const int a = m & 3;
    const int bs = m >> 2;
    const float* src = ad + ((size_t)((a * B_ + (bs >> 11)) * S_) + (bs & (S_ - 1))) * H_;
    const float4 v = ((const float4*)src)[threadIdx.x];
    const size_t idx = (size_t)m * H_ + threadIdx.x * 4;

    __nv_bfloat16 h0 = __float2bfloat16(v.x), h1 = __float2bfloat16(v.y);
    __nv_bfloat16 h2 = __float2bfloat16(v.z), h3 = __float2bfloat16(v.w);
    __nv_bfloat16 l0 = __float2bfloat16(v.x - __bfloat162float(h0));
    __nv_bfloat16 l1 = __float2bfloat16(v.y - __bfloat162float(h1));
    __nv_bfloat16 l2 = __float2bfloat16(v.z - __bfloat162float(h2));
    __nv_bfloat16 l3 = __float2bfloat16(v.w - __bfloat162float(h3));
    __nv_bfloat162* ph = (__nv_bfloat162*)&g_xhi[idx];
    __nv_bfloat162* pl = (__nv_bfloat162*)&g_xlo[idx];
    __nv_bfloat162 t;
    t.x = h0; t.y = h1; ph[0] = t;
    t.x = h2; t.y = h3; ph[1] = t;
    t.x = l0; t.y = l1; pl[0] = t;
    t.x = l2; t.y = l3; pl[1] = t;
}

__global__ __launch_bounds__(256) void conv_w(const float* __restrict__ Wq,
                                              const float* __restrict__ Wk,
                                              const float* __restrict__ Wv,
                                              const float* __restrict__ Wo)
{
    const int z = blockIdx.z;
    const float* W = (z == 0) ? Wq : (z == 1) ? Wk : (z == 2) ? Wv : Wo;
    __nv_bfloat16* oh = g_wThi[z];
    __nv_bfloat16* ol = g_wTlo[z];
    __shared__ float tl[32][33];
    const int tx = threadIdx.x, ty = threadIdx.y;
    const int n0 = blockIdx.x * 32, k0 = blockIdx.y * 32;
#pragma unroll
    for (int i = 0; i < 4; i++)
        tl[ty + 8 * i][tx] = W[(size_t)(k0 + ty + 8 * i) * H_ + n0 + tx];
    __syncthreads();
#pragma unroll
    for (int i = 0; i < 4; i++) {
        const float v = tl[tx][ty + 8 * i];
        const __nv_bfloat16 h = __float2bfloat16(v);
        const __nv_bfloat16 l = __float2bfloat16(v - __bfloat162float(h));
        const size_t o = (size_t)(n0 + ty + 8 * i) * H_ + k0 + tx;
        oh[o] = h;
        ol[o] = l;
    }
}

// ---------------------------------------------------------------------------
// mma.sync bf16 3-split GEMM: C[m,n] = A[m,:] . WT[n,:] + bias (+ resid)
// CTA 128x128, BK=64, 2-stage cp.async double buffer, 8 warps (2x4),
// warp tile 64x32, m16n8k16 HMMA with fp32 accumulation.
// MODE 0: A = g_xhi/g_xlo, B = g_wThi[z]/g_wTlo[z] (z = blockIdx.z),
//         C = g_Q/g_K/g_V by z, bias = bq/bk/bv.
// MODE 1: A = g_phi/g_plo, B = g_wThi[3], C = g_fused, + residual.
// ---------------------------------------------------------------------------
#define AHI_OFF 0
#define ALO_OFF 16384
#define BHI_OFF 32768
#define BLO_OFF 49152
#define STAGE_B 65536
#define DSMEM_B (2 * STAGE_B + 1024)

// SW128 swizzled offset of (row, 16B-chunk) within a 128-row x 128B tile
__device__ __forceinline__ uint32_t swoff(int r, int c16) {
    return (uint32_t)(r * 128 + ((c16 ^ (r & 7)) << 4));
}

__device__ __forceinline__ void load_chunk(uint32_t sb,
                                           const __nv_bfloat16* __restrict__ Ahi,
                                           const __nv_bfloat16* __restrict__ Alo,
                                           const __nv_bfloat16* __restrict__ Bhi,
                                           const __nv_bfloat16* __restrict__ Blo,
                                           int t, int mt, int nt, int c)
{
    const int kof = c * 64;
#pragma unroll
    for (int i = 0; i < 4; i++) {
        const int seg = t + i * 256;          // 0..1023
        const int r = seg >> 3, c16 = seg & 7;
        const uint32_t sw = swoff(r, c16);
        const size_t goA = (size_t)(mt * 128 + r) * H_ + kof + c16 * 8;
        cp16(sb + AHI_OFF + sw, Ahi + goA);
        cp16(sb + ALO_OFF + sw, Alo + goA);
        const size_t goB = (size_t)(nt * 128 + r) * H_ + kof + c16 * 8;
        cp16(sb + BHI_OFF + sw, Bhi + goB);
        cp16(sb + BLO_OFF + sw, Blo + goB);
    }
}

template <int MODE>
__global__ __launch_bounds__(256, 1)
void gemm_mma(const float* __restrict__ b0p, const float* __restrict__ b1p,
              const float* __restrict__ b2p, const float* __restrict__ resid)
{
    extern __shared__ __align__(1024) char dsm[];
    const uint32_t sbase = (smem_u32(dsm) + 1023) & ~1023u;

    const int t  = threadIdx.x;
    const int nt = blockIdx.x;
    const int mt = blockIdx.y;
    const int z  = (MODE == 0) ? blockIdx.z : 3;

    const __nv_bfloat16* Ahi = (MODE == 0) ? g_xhi : g_phi;
    const __nv_bfloat16* Alo = (MODE == 0) ? g_xlo : g_plo;
    const __nv_bfloat16* Bhi = g_wThi[z];
    const __nv_bfloat16* Blo = g_wTlo[z];
    float* C = (MODE == 1) ? g_fused : (z == 0) ? g_Q : (z == 1) ? g_K : g_V;
    const float* bias = (MODE == 1) ? b0p : (z == 0) ? b0p : (z == 1) ? b1p : b2p;

    const int lane = t & 31;
    const int w  = t >> 5;
    const int wm = w >> 2;      // 0..1
    const int wn = w & 3;       // 0..3

    // ldmatrix per-lane bases (matrix j = lane>>3, row-in-matrix = lane&7)
    const int xorv = lane & 7;
    const uint32_t aOff = (uint32_t)((wm * 64 + ((lane >> 3) & 1) * 8 + (lane & 7)) * 128);
    const int aCk = lane >> 4;           // k-chunk half (j>>1)
    const uint32_t bOff = (uint32_t)((wn * 32 + ((lane >> 4) << 3) + (lane & 7)) * 128);
    const int bCk = (lane >> 3) & 1;     // k-chunk half (j&1)

    float acc[4][4][4];
#pragma unroll
    for (int mi = 0; mi < 4; mi++)
#pragma unroll
        for (int ni = 0; ni < 4; ni++)
#pragma unroll
            for (int r = 0; r < 4; r++) acc[mi][ni][r] = 0.0f;

    load_chunk(sbase, Ahi, Alo, Bhi, Blo, t, mt, nt, 0);
    cp_commit();

    const int NC = H_ / 64;   // 16
    for (int c = 0; c < NC; c++) {
        if (c + 1 < NC) {
            load_chunk(sbase + ((c + 1) & 1) * STAGE_B, Ahi, Alo, Bhi, Blo, t, mt, nt, c + 1);
            cp_commit();
            asm volatile("cp.async.wait_group 1;" ::: "memory");
        } else {
            asm volatile("cp.async.wait_group 0;" ::: "memory");
        }
        __syncthreads();

        const uint32_t sb = sbase + (c & 1) * STAGE_B;
#pragma unroll
        for (int ks = 0; ks < 4; ks++) {
            uint32_t ah[4][4], al[4][4];
            uint32_t bh[4][2], bl[4][2];
            const uint32_t xa = (uint32_t)(((ks * 2 + aCk) ^ xorv) << 4);
            const uint32_t xb = (uint32_t)(((ks * 2 + bCk) ^ xorv) << 4);
#pragma unroll
            for (int mi = 0; mi < 4; mi++) {
                LDM4(ah[mi], sb + AHI_OFF + aOff + mi * 2048 + xa);
                LDM4(al[mi], sb + ALO_OFF + aOff + mi * 2048 + xa);
            }
#pragma unroll
            for (int pi = 0; pi < 2; pi++) {
                uint32_t tmp[4];
                LDM4(tmp, sb + BHI_OFF + bOff + pi * 2048 + xb);
                bh[2 * pi][0] = tmp[0]; bh[2 * pi][1] = tmp[1];
                bh[2 * pi + 1][0] = tmp[2]; bh[2 * pi + 1][1] = tmp[3];
                LDM4(tmp, sb + BLO_OFF + bOff + pi * 2048 + xb);
                bl[2 * pi][0] = tmp[0]; bl[2 * pi][1] = tmp[1];
                bl[2 * pi + 1][0] = tmp[2]; bl[2 * pi + 1][1] = tmp[3];
            }
#pragma unroll
            for (int mi = 0; mi < 4; mi++)
#pragma unroll
                for (int ni = 0; ni < 4; ni++) {
                    MMA16816(acc[mi][ni], ah[mi], bh[ni][0], bh[ni][1]);
                    MMA16816(acc[mi][ni], ah[mi], bl[ni][0], bl[ni][1]);
                    MMA16816(acc[mi][ni], al[mi], bh[ni][0], bh[ni][1]);
                }
        }
        __syncthreads();
    }

    // Epilogue: bias (+ residual)
#pragma unroll
    for (int mi = 0; mi < 4; mi++) {
        const int r0 = mt * 128 + wm * 64 + mi * 16 + (lane >> 2);
        const int r1 = r0 + 8;
#pragma unroll
        for (int ni = 0; ni < 4; ni++) {
            const int col = nt * 128 + wn * 32 + ni * 8 + (lane & 3) * 2;
            const float2 bb = *(const float2*)(bias + col);
            float2 v01, v23;
            v01.x = acc[mi][ni][0] + bb.x; v01.y = acc[mi][ni][1] + bb.y;
            v23.x = acc[mi][ni][2] + bb.x; v23.y = acc[mi][ni][3] + bb.y;
            if (MODE == 1) {
                const float2 ra = *(const float2*)(resid + (size_t)r0 * H_ + col);
                const float2 rb = *(const float2*)(resid + (size_t)r1 * H_ + col);
                v01.x += ra.x; v01.y += ra.y;
                v23.x += rb.x; v23.y += rb.y;
            }
            *(float2*)(C + (size_t)r0 * H_ + col) = v01;
            *(float2*)(C + (size_t)r1 * H_ + col) = v23;
        }
    }
}

// ---------------------------------------------------------------------------
// Attention over adapter axis + mean pool -> bf16 hi/lo for O-GEMM
// ---------------------------------------------------------------------------
__global__ __launch_bounds__(256)
void attn_pool_kernel()
{
    const int warp = threadIdx.x >> 5;
    const int lane = threadIdx.x & 31;
    const int unit = blockIdx.x * 8 + warp;
    const int bs = unit >> 4;
    const int h  = unit & 15;

    const size_t base = (size_t)(bs * A_) * H_ + h * HD_;
    float q[A_][2], k[A_][2], v[A_][2];
#pragma unroll
    for (int a = 0; a < A_; a++) {
        const float* qp = g_Q + base + a * H_;
        const float* kp = g_K + base + a * H_;
        const float* vp = g_V + base + a * H_;
        q[a][0] = qp[lane]; q[a][1] = qp[lane + 32];
        k[a][0] = kp[lane]; k[a][1] = kp[lane + 32];
        v[a][0] = vp[lane]; v[a][1] = vp[lane + 32];
    }

    float sc[A_][A_];
#pragma unroll
    for (int i = 0; i < A_; i++)
#pragma unroll
        for (int j = 0; j < A_; j++)
            sc[i][j] = q[i][0] * k[j][0] + q[i][1] * k[j][1];

#pragma unroll
    for (int off = 16; off > 0; off >>= 1)
#pragma unroll
        for (int i = 0; i < A_; i++)
#pragma unroll
            for (int j = 0; j < A_; j++)
                sc[i][j] += __shfl_xor_sync(0xffffffffu, sc[i][j], off);

    float colw[A_] = {0.f, 0.f, 0.f, 0.f};
#pragma unroll
    for (int i = 0; i < A_; i++) {
        float s0 = sc[i][0] * 0.125f, s1 = sc[i][1] * 0.125f;
        float s2 = sc[i][2] * 0.125f, s3 = sc[i][3] * 0.125f;
        const float mx = fmaxf(fmaxf(s0, s1), fmaxf(s2, s3));
        const float e0 = __expf(s0 - mx), e1 = __expf(s1 - mx);
        const float e2 = __expf(s2 - mx), e3 = __expf(s3 - mx);
        const float inv = 1.0f / (e0 + e1 + e2 + e3);
        colw[0] += e0 * inv; colw[1] += e1 * inv;
        colw[2] += e2 * inv; colw[3] += e3 * inv;
    }

    float o0 = 0.f, o1 = 0.f;
#pragma unroll
    for (int j = 0; j < A_; j++) {
        const float c = colw[j] * 0.25f;
        o0 = fmaf(c, v[j][0], o0);
        o1 = fmaf(c, v[j][1], o1);
    }
    const size_t op = (size_t)bs * H_ + h * HD_;
    const __nv_bfloat16 h0 = __float2bfloat16(o0);
    const __nv_bfloat16 h1 = __float2bfloat16(o1);
    g_phi[op + lane]      = h0;
    g_phi[op + lane + 32] = h1;
    g_plo[op + lane]      = __float2bfloat16(o0 - __bfloat162float(h0));
    g_plo[op + lane + 32] = __float2bfloat16(o1 - __bfloat162float(h1));
}

// ---------------------------------------------------------------------------
// LayerNorm over H=1024 per row
// ---------------------------------------------------------------------------
__global__ __launch_bounds__(256)
void ln_kernel(const float* __restrict__ gamma,
               const float* __restrict__ beta,
               float* __restrict__ out)
{
    const int row = blockIdx.x;
    const int t = threadIdx.x;

    const float4 x = ((const float4*)(g_fused + (size_t)row * H_))[t];
    float s  = x.x + x.y + x.z + x.w;
    float ss = x.x * x.x + x.y * x.y + x.z * x.z + x.w * x.w;
#pragma unroll
    for (int off = 16; off > 0; off >>= 1) {
        s  += __shfl_xor_sync(0xffffffffu, s,  off);
        ss += __shfl_xor_sync(0xffffffffu, ss, off);
    }
    __shared__ float sh_s[8], sh_ss[8];
    if ((t & 31) == 0) { sh_s[t >> 5] = s; sh_ss[t >> 5] = ss; }
    __syncthreads();
    float tot = 0.f, tot2 = 0.f;
#pragma unroll
    for (int w = 0; w < 8; w++) { tot += sh_s[w]; tot2 += sh_ss[w]; }

    const float mu   = tot * (1.0f / H_);
    const float var  = tot2 * (1.0f / H_) - mu * mu;
    const float rstd = rsqrtf(var + 1e-5f);

    const float4 g = ((const float4*)gamma)[t];
    const float4 b = ((const float4*)beta)[t];
    float4 y;
    y.x = (x.x - mu) * rstd * g.x + b.x;
    y.y = (x.y - mu) * rstd * g.y + b.y;
    y.z = (x.z - mu) * rstd * g.z + b.z;
    y.w = (x.w - mu) * rstd * g.w + b.w;
    ((float4*)(out + (size_t)row * H_))[t] = y;
}

// ---------------------------------------------------------------------------
// Launch
// ---------------------------------------------------------------------------
extern "C" void kernel_launch(void* const* d_in, const int* in_sizes, int n_in,
                              void* d_out, int out_size)
{
    (void)in_sizes; (void)n_in; (void)out_size;
    const float* adapter = (const float*)d_in[0];
    const float* Wq = (const float*)d_in[1];
    const float* bq = (const float*)d_in[2];
    const float* Wk = (const float*)d_in[3];
    const float* bk = (const float*)d_in[4];
    const float* Wv = (const float*)d_in[5];
    const float* bv = (const float*)d_in[6];
    const float* Wo = (const float*)d_in[7];
    const float* bo = (const float*)d_in[8];
    const float* gamma = (const float*)d_in[9];
    const float* beta  = (const float*)d_in[10];
    float* out = (float*)d_out;

    cudaFuncSetAttribute(gemm_mma<0>, cudaFuncAttributeMaxDynamicSharedMemorySize, DSMEM_B);
    cudaFuncSetAttribute(gemm_mma<1>, cudaFuncAttributeMaxDynamicSharedMemorySize, DSMEM_B);

    conv_x<<<M1_, 256>>>(adapter);
    conv_w<<<dim3(32, 32, 4), dim3(32, 8)>>>(Wq, Wk, Wv, Wo);

    const dim3 gq(H_ / 128, M1_ / 128, 3);   // (8, 256, 3)
    gemm_mma<0><<<gq, 256, DSMEM_B>>>(bq, bk, bv, nullptr);

    attn_pool_kernel<<<(BS_ * NH_) / 8, 256>>>();

    const dim3 go(H_ / 128, BS_ / 128, 1);   // (8, 64)
    gemm_mma<1><<<go, 256, DSMEM_B>>>(bo, nullptr, nullptr, adapter);

    ln_kernel<<<BS_, 256>>>(gamma, beta, out);
}

// round 5
// speedup vs baseline: 2.8802x; 1.0009x over previous
#include <cuda_runtime.h>
#include <cuda_bf16.h>
#include <cstdint>

#define A_  4
#define B_  4
#define S_  2048
#define H_  1024
#define NH_ 16
#define HD_ 64
#define BS_ (B_ * S_)     // 8192
#define M1_ (BS_ * A_)    // 32768

// ---------------------------------------------------------------------------
// Scratch (device globals)
// ---------------------------------------------------------------------------
__device__ __align__(256) __nv_bfloat16 g_xhi[M1_ * H_];    // 64 MB
__device__ __align__(256) __nv_bfloat16 g_xlo[M1_ * H_];    // 64 MB
__device__ __align__(256) __nv_bfloat16 g_wThi[4][H_ * H_]; // 8 MB  ([n][k])
__device__ __align__(256) __nv_bfloat16 g_wTlo[4][H_ * H_]; // 8 MB
__device__ __align__(256) float g_Q[M1_ * H_];              // 128 MB
__device__ __align__(256) float g_K[M1_ * H_];              // 128 MB
__device__ __align__(256) float g_V[M1_ * H_];              // 128 MB
__device__ __align__(256) __nv_bfloat16 g_phi[BS_ * H_];    // 16 MB
__device__ __align__(256) __nv_bfloat16 g_plo[BS_ * H_];    // 16 MB
__device__ __align__(256) float g_fused[BS_ * H_];          // 32 MB

// ---------------------------------------------------------------------------
// PTX helpers (all sm_80+ / base-target legal; NO tcgen05)
// ---------------------------------------------------------------------------
__device__ __forceinline__ uint32_t smem_u32(const void* p) {
    uint32_t a;
    asm("{ .reg .u64 t; cvta.to.shared.u64 t, %1; cvt.u32.u64 %0, t; }" : "=r"(a) : "l"(p));
    return a;
}
__device__ __forceinline__ void cp16(uint32_t s, const void* g) {
    asm volatile("cp.async.cg.shared.global [%0], [%1], 16;" :: "r"(s), "l"(g));
}
__device__ __forceinline__ void cp_commit() {
    asm volatile("cp.async.commit_group;" ::: "memory");
}

#define LDM4(d, addr) \
    asm volatile("ldmatrix.sync.aligned.m8n8.x4.shared.b16 {%0,%1,%2,%3}, [%4];" \
                 : "=r"((d)[0]), "=r"((d)[1]), "=r"((d)[2]), "=r"((d)[3]) : "r"(addr))

#define MMA16816(d, a, b0v, b1v) \
    asm volatile("mma.sync.aligned.m16n8k16.row.col.f32.bf16.bf16.f32 " \
                 "{%0,%1,%2,%3}, {%4,%5,%6,%7}, {%8,%9}, {%0,%1,%2,%3};" \
                 : "+f"((d)[0]), "+f"((d)[1]), "+f"((d)[2]), "+f"((d)[3]) \
                 : "r"((a)[0]), "r"((a)[1]), "r"((a)[2]), "r"((a)[3]), \
                   "r"(b0v), "r"(b1v))

// ---------------------------------------------------------------------------
// Conversion kernels
// ---------------------------------------------------------------------------
__global__ __launch_bounds__(256) void conv_x(const float* __restrict__ ad)
{
    const int m = blockIdx.x;
    const int a = m & 3;
    const int bs = m >> 2;
    const float* src = ad + ((size_t)((a * B_ + (bs >> 11)) * S_) + (bs & (S_ - 1))) * H_;
    const float4 v = ((const float4*)src)[threadIdx.x];
    const size_t idx = (size_t)m * H_ + threadIdx.x * 4;

    __nv_bfloat16 h0 = __float2bfloat16(v.x), h1 = __float2bfloat16(v.y);
    __nv_bfloat16 h2 = __float2bfloat16(v.z), h3 = __float2bfloat16(v.w);
    __nv_bfloat16 l0 = __float2bfloat16(v.x - __bfloat162float(h0));
    __nv_bfloat16 l1 = __float2bfloat16(v.y - __bfloat162float(h1));
    __nv_bfloat16 l2 = __float2bfloat16(v.z - __bfloat162float(h2));
    __nv_bfloat16 l3 = __float2bfloat16(v.w - __bfloat162float(h3));
    __nv_bfloat162* ph = (__nv_bfloat162*)&g_xhi[idx];
    __nv_bfloat162* pl = (__nv_bfloat162*)&g_xlo[idx];
    __nv_bfloat162 t;
    t.x = h0; t.y = h1; ph[0] = t;
    t.x = h2; t.y = h3; ph[1] = t;
    t.x = l0; t.y = l1; pl[0] = t;
    t.x = l2; t.y = l3; pl[1] = t;
}

__global__ __launch_bounds__(256) void conv_w(const float* __restrict__ Wq,
                                              const float* __restrict__ Wk,
                                              const float* __restrict__ Wv,
                                              const float* __restrict__ Wo)
{
    const int z = blockIdx.z;
    const float* W = (z == 0) ? Wq : (z == 1) ? Wk : (z == 2) ? Wv : Wo;
    __nv_bfloat16* oh = g_wThi[z];
    __nv_bfloat16* ol = g_wTlo[z];
    __shared__ float tl[32][33];
    const int tx = threadIdx.x, ty = threadIdx.y;
    const int n0 = blockIdx.x * 32, k0 = blockIdx.y * 32;
#pragma unroll
    for (int i = 0; i < 4; i++)
        tl[ty + 8 * i][tx] = W[(size_t)(k0 + ty + 8 * i) * H_ + n0 + tx];
    __syncthreads();
#pragma unroll
    for (int i = 0; i < 4; i++) {
        const float v = tl[tx][ty + 8 * i];
        const __nv_bfloat16 h = __float2bfloat16(v);
        const __nv_bfloat16 l = __float2bfloat16(v - __bfloat162float(h));
        const size_t o = (size_t)(n0 + ty + 8 * i) * H_ + k0 + tx;
        oh[o] = h;
        ol[o] = l;
    }
}

// ---------------------------------------------------------------------------
// mma.sync bf16 3-split GEMM: C[m,n] = A[m,:] . WT[n,:] + bias (+ resid)
// CTA 128x128, BK=64, 2-stage cp.async double buffer, 8 warps (2x4),
// warp tile 64x32, m16n8k16 HMMA with fp32 accumulation.
// Pass-major mma issue order: 16 independent accumulators between reuses
// of the same acc fragment (breaks the RAW chain that stalled R4).
// ---------------------------------------------------------------------------
#define AHI_OFF 0
#define ALO_OFF 16384
#define BHI_OFF 32768
#define BLO_OFF 49152
#define STAGE_B 65536
#define DSMEM_B (2 * STAGE_B + 1024)

// SW128 swizzled offset of (row, 16B-chunk) within a 128-row x 128B tile
__device__ __forceinline__ uint32_t swoff(int r, int c16) {
    return (uint32_t)(r * 128 + ((c16 ^ (r & 7)) << 4));
}

__device__ __forceinline__ void load_chunk(uint32_t sb,
                                           const __nv_bfloat16* __restrict__ Ahi,
                                           const __nv_bfloat16* __restrict__ Alo,
                                           const __nv_bfloat16* __restrict__ Bhi,
                                           const __nv_bfloat16* __restrict__ Blo,
                                           int t, int mt, int nt, int c)
{
    const int kof = c * 64;
#pragma unroll
    for (int i = 0; i < 4; i++) {
        const int seg = t + i * 256;          // 0..1023
        const int r = seg >> 3, c16 = seg & 7;
        const uint32_t sw = swoff(r, c16);
        const size_t goA = (size_t)(mt * 128 + r) * H_ + kof + c16 * 8;
        cp16(sb + AHI_OFF + sw, Ahi + goA);
        cp16(sb + ALO_OFF + sw, Alo + goA);
        const size_t goB = (size_t)(nt * 128 + r) * H_ + kof + c16 * 8;
        cp16(sb + BHI_OFF + sw, Bhi + goB);
        cp16(sb + BLO_OFF + sw, Blo + goB);
    }
}

template <int MODE>
__global__ __launch_bounds__(256, 1)
void gemm_mma(const float* __restrict__ b0p, const float* __restrict__ b1p,
              const float* __restrict__ b2p, const float* __restrict__ resid)
{
    extern __shared__ __align__(1024) char dsm[];
    const uint32_t sbase = (smem_u32(dsm) + 1023) & ~1023u;

    const int t  = threadIdx.x;
    const int nt = blockIdx.x;
    const int mt = blockIdx.y;
    const int z  = (MODE == 0) ? blockIdx.z : 3;

    const __nv_bfloat16* Ahi = (MODE == 0) ? g_xhi : g_phi;
    const __nv_bfloat16* Alo = (MODE == 0) ? g_xlo : g_plo;
    const __nv_bfloat16* Bhi = g_wThi[z];
    const __nv_bfloat16* Blo = g_wTlo[z];
    float* C = (MODE == 1) ? g_fused : (z == 0) ? g_Q : (z == 1) ? g_K : g_V;
    const float* bias = (MODE == 1) ? b0p : (z == 0) ? b0p : (z == 1) ? b1p : b2p;

    const int lane = t & 31;
    const int w  = t >> 5;
    const int wm = w >> 2;      // 0..1
    const int wn = w & 3;       // 0..3

    // ldmatrix per-lane bases
    const int xorv = lane & 7;
    const uint32_t aOff = (uint32_t)((wm * 64 + ((lane >> 3) & 1) * 8 + (lane & 7)) * 128);
    const int aCk = lane >> 4;           // k-chunk half
    const uint32_t bOff = (uint32_t)((wn * 32 + ((lane >> 4) << 3) + (lane & 7)) * 128);
    const int bCk = (lane >> 3) & 1;     // k-chunk half

    float acc[4][4][4];
#pragma unroll
    for (int mi = 0; mi < 4; mi++)
#pragma unroll
        for (int ni = 0; ni < 4; ni++)
#pragma unroll
            for (int r = 0; r < 4; r++) acc[mi][ni][r] = 0.0f;

    load_chunk(sbase, Ahi, Alo, Bhi, Blo, t, mt, nt, 0);
    cp_commit();

    const int NC = H_ / 64;   // 16
    for (int c = 0; c < NC; c++) {
        if (c + 1 < NC) {
            load_chunk(sbase + ((c + 1) & 1) * STAGE_B, Ahi, Alo, Bhi, Blo, t, mt, nt, c + 1);
            cp_commit();
            asm volatile("cp.async.wait_group 1;" ::: "memory");
        } else {
            asm volatile("cp.async.wait_group 0;" ::: "memory");
        }
        __syncthreads();

        const uint32_t sb = sbase + (c & 1) * STAGE_B;
#pragma unroll
        for (int ks = 0; ks < 4; ks++) {
            uint32_t ah[4][4], al[4][4];
            uint32_t bh[4][2], bl[4][2];
            const uint32_t xa = (uint32_t)(((ks * 2 + aCk) ^ xorv) << 4);
            const uint32_t xb = (uint32_t)(((ks * 2 + bCk) ^ xorv) << 4);
#pragma unroll
            for (int mi = 0; mi < 4; mi++) {
                LDM4(ah[mi], sb + AHI_OFF + aOff + mi * 2048 + xa);
                LDM4(al[mi], sb + ALO_OFF + aOff + mi * 2048 + xa);
            }
#pragma unroll
            for (int pi = 0; pi < 2; pi++) {
                uint32_t tmp[4];
                LDM4(tmp, sb + BHI_OFF + bOff + pi * 2048 + xb);
                bh[2 * pi][0] = tmp[0]; bh[2 * pi][1] = tmp[1];
                bh[2 * pi + 1][0] = tmp[2]; bh[2 * pi + 1][1] = tmp[3];
                LDM4(tmp, sb + BLO_OFF + bOff + pi * 2048 + xb);
                bl[2 * pi][0] = tmp[0]; bl[2 * pi][1] = tmp[1];
                bl[2 * pi + 1][0] = tmp[2]; bl[2 * pi + 1][1] = tmp[3];
            }
            // Pass-major issue: all 16 independent accs per pass.
            // Same-acc reuse distance = 16 mma >= HMMA latency -> no RAW stalls.
#pragma unroll
            for (int mi = 0; mi < 4; mi++)
#pragma unroll
                for (int ni = 0; ni < 4; ni++)
                    MMA16816(acc[mi][ni], ah[mi], bh[ni][0], bh[ni][1]);
#pragma unroll
            for (int mi = 0; mi < 4; mi++)
#pragma unroll
                for (int ni = 0; ni < 4; ni++)
                    MMA16816(acc[mi][ni], ah[mi], bl[ni][0], bl[ni][1]);
#pragma unroll
            for (int mi = 0; mi < 4; mi++)
#pragma unroll
                for (int ni = 0; ni < 4; ni++)
                    MMA16816(acc[mi][ni], al[mi], bh[ni][0], bh[ni][1]);
        }
        __syncthreads();
    }

    // Epilogue: bias (+ residual)
#pragma unroll
    for (int mi = 0; mi < 4; mi++) {
        const int r0 = mt * 128 + wm * 64 + mi * 16 + (lane >> 2);
        const int r1 = r0 + 8;
#pragma unroll
        for (int ni = 0; ni < 4; ni++) {
            const int col = nt * 128 + wn * 32 + ni * 8 + (lane & 3) * 2;
            const float2 bb = *(const float2*)(bias + col);
            float2 v01, v23;
            v01.x = acc[mi][ni][0] + bb.x; v01.y = acc[mi][ni][1] + bb.y;
            v23.x = acc[mi][ni][2] + bb.x; v23.y = acc[mi][ni][3] + bb.y;
            if (MODE == 1) {
                const float2 ra = *(const float2*)(resid + (size_t)r0 * H_ + col);
                const float2 rb = *(const float2*)(resid + (size_t)r1 * H_ + col);
                v01.x += ra.x; v01.y += ra.y;
                v23.x += rb.x; v23.y += rb.y;
            }
            *(float2*)(C + (size_t)r0 * H_ + col) = v01;
            *(float2*)(C + (size_t)r1 * H_ + col) = v23;
        }
    }
}

// ---------------------------------------------------------------------------
// Attention over adapter axis + mean pool -> bf16 hi/lo for O-GEMM
// ---------------------------------------------------------------------------
__global__ __launch_bounds__(256)
void attn_pool_kernel()
{
    const int warp = threadIdx.x >> 5;
    const int lane = threadIdx.x & 31;
    const int unit = blockIdx.x * 8 + warp;
    const int bs = unit >> 4;
    const int h  = unit & 15;

    const size_t base = (size_t)(bs * A_) * H_ + h * HD_;
    float q[A_][2], k[A_][2], v[A_][2];
#pragma unroll
    for (int a = 0; a < A_; a++) {
        const float* qp = g_Q + base + a * H_;
        const float* kp = g_K + base + a * H_;
        const float* vp = g_V + base + a * H_;
        q[a][0] = qp[lane]; q[a][1] = qp[lane + 32];
        k[a][0] = kp[lane]; k[a][1] = kp[lane + 32];
        v[a][0] = vp[lane]; v[a][1] = vp[lane + 32];
    }

    float sc[A_][A_];
#pragma unroll
    for (int i = 0; i < A_; i++)
#pragma unroll
        for (int j = 0; j < A_; j++)
            sc[i][j] = q[i][0] * k[j][0] + q[i][1] * k[j][1];

#pragma unroll
    for (int off = 16; off > 0; off >>= 1)
#pragma unroll
        for (int i = 0; i < A_; i++)
#pragma unroll
            for (int j = 0; j < A_; j++)
                sc[i][j] += __shfl_xor_sync(0xffffffffu, sc[i][j], off);

    float colw[A_] = {0.f, 0.f, 0.f, 0.f};
#pragma unroll
    for (int i = 0; i < A_; i++) {
        float s0 = sc[i][0] * 0.125f, s1 = sc[i][1] * 0.125f;
        float s2 = sc[i][2] * 0.125f, s3 = sc[i][3] * 0.125f;
        const float mx = fmaxf(fmaxf(s0, s1), fmaxf(s2, s3));
        const float e0 = __expf(s0 - mx), e1 = __expf(s1 - mx);
        const float e2 = __expf(s2 - mx), e3 = __expf(s3 - mx);
        const float inv = 1.0f / (e0 + e1 + e2 + e3);
        colw[0] += e0 * inv; colw[1] += e1 * inv;
        colw[2] += e2 * inv; colw[3] += e3 * inv;
    }

    float o0 = 0.f, o1 = 0.f;
#pragma unroll
    for (int j = 0; j < A_; j++) {
        const float c = colw[j] * 0.25f;
        o0 = fmaf(c, v[j][0], o0);
        o1 = fmaf(c, v[j][1], o1);
    }
    const size_t op = (size_t)bs * H_ + h * HD_;
    const __nv_bfloat16 h0 = __float2bfloat16(o0);
    const __nv_bfloat16 h1 = __float2bfloat16(o1);
    g_phi[op + lane]      = h0;
    g_phi[op + lane + 32] = h1;
    g_plo[op + lane]      = __float2bfloat16(o0 - __bfloat162float(h0));
    g_plo[op + lane + 32] = __float2bfloat16(o1 - __bfloat162float(h1));
}

// ---------------------------------------------------------------------------
// LayerNorm over H=1024 per row
// ---------------------------------------------------------------------------
__global__ __launch_bounds__(256)
void ln_kernel(const float* __restrict__ gamma,
               const float* __restrict__ beta,
               float* __restrict__ out)
{
    const int row = blockIdx.x;
    const int t = threadIdx.x;

    const float4 x = ((const float4*)(g_fused + (size_t)row * H_))[t];
    float s  = x.x + x.y + x.z + x.w;
    float ss = x.x * x.x + x.y * x.y + x.z * x.z + x.w * x.w;
#pragma unroll
    for (int off = 16; off > 0; off >>= 1) {
        s  += __shfl_xor_sync(0xffffffffu, s,  off);
        ss += __shfl_xor_sync(0xffffffffu, ss, off);
    }
    __shared__ float sh_s[8], sh_ss[8];
    if ((t & 31) == 0) { sh_s[t >> 5] = s; sh_ss[t >> 5] = ss; }
    __syncthreads();
    float tot = 0.f, tot2 = 0.f;
#pragma unroll
    for (int w = 0; w < 8; w++) { tot += sh_s[w]; tot2 += sh_ss[w]; }

    const float mu   = tot * (1.0f / H_);
    const float var  = tot2 * (1.0f / H_) - mu * mu;
    const float rstd = rsqrtf(var + 1e-5f);

    const float4 g = ((const float4*)gamma)[t];
    const float4 b = ((const float4*)beta)[t];
    float4 y;
    y.x = (x.x - mu) * rstd * g.x + b.x;
    y.y = (x.y - mu) * rstd * g.y + b.y;
    y.z = (x.z - mu) * rstd * g.z + b.z;
    y.w = (x.w - mu) * rstd * g.w + b.w;
    ((float4*)(out + (size_t)row * H_))[t] = y;
}

// ---------------------------------------------------------------------------
// Launch
// ---------------------------------------------------------------------------
extern "C" void kernel_launch(void* const* d_in, const int* in_sizes, int n_in,
                              void* d_out, int out_size)
{
    (void)in_sizes; (void)n_in; (void)out_size;
    const float* adapter = (const float*)d_in[0];
    const float* Wq = (const float*)d_in[1];
    const float* bq = (const float*)d_in[2];
    const float* Wk = (const float*)d_in[3];
    const float* bk = (const float*)d_in[4];
    const float* Wv = (const float*)d_in[5];
    const float* bv = (const float*)d_in[6];
    const float* Wo = (const float*)d_in[7];
    const float* bo = (const float*)d_in[8];
    const float* gamma = (const float*)d_in[9];
    const float* beta  = (const float*)d_in[10];
    float* out = (float*)d_out;

    cudaFuncSetAttribute(gemm_mma<0>, cudaFuncAttributeMaxDynamicSharedMemorySize, DSMEM_B);
    cudaFuncSetAttribute(gemm_mma<1>, cudaFuncAttributeMaxDynamicSharedMemorySize, DSMEM_B);

    conv_x<<<M1_, 256>>>(adapter);
    conv_w<<<dim3(32, 32, 4), dim3(32, 8)>>>(Wq, Wk, Wv, Wo);

    const dim3 gq(H_ / 128, M1_ / 128, 3);   // (8, 256, 3)
    gemm_mma<0><<<gq, 256, DSMEM_B>>>(bq, bk, bv, nullptr);

    attn_pool_kernel<<<(BS_ * NH_) / 8, 256>>>();

    const dim3 go(H_ / 128, BS_ / 128, 1);   // (8, 64)
    gemm_mma<1><<<go, 256, DSMEM_B>>>(bo, nullptr, nullptr, adapter);

    ln_kernel<<<BS_, 256>>>(gamma, beta, out);
}

// round 6
// speedup vs baseline: 5.7403x; 1.9931x over previous
#include <cuda_runtime.h>
#include <cuda_fp16.h>
#include <cstdint>

#define A_  4
#define B_  4
#define S_  2048
#define H_  1024
#define NH_ 16
#define HD_ 64
#define BS_ (B_ * S_)     // 8192
#define M1_ (BS_ * A_)    // 32768

// ---------------------------------------------------------------------------
// Scratch (device globals)
// ---------------------------------------------------------------------------
__device__ __align__(256) __half g_xh[M1_ * H_];        // 64 MB  (permuted x, fp16)
__device__ __align__(256) __half g_wTh[4][H_ * H_];     // 8 MB   (W^T [n][k], fp16)
__device__ __align__(256) float g_Q[M1_ * H_];          // 128 MB
__device__ __align__(256) float g_K[M1_ * H_];          // 128 MB
__device__ __align__(256) float g_V[M1_ * H_];          // 128 MB
__device__ __align__(256) __half g_ph[BS_ * H_];        // 16 MB  (pooled, fp16)
__device__ __align__(256) float g_fused[BS_ * H_];      // 32 MB

// ---------------------------------------------------------------------------
// PTX helpers (sm_80+ legal; no tcgen05 — base target rejects it)
// ---------------------------------------------------------------------------
__device__ __forceinline__ uint32_t smem_u32(const void* p) {
    uint32_t a;
    asm("{ .reg .u64 t; cvta.to.shared.u64 t, %1; cvt.u32.u64 %0, t; }" : "=r"(a) : "l"(p));
    return a;
}
__device__ __forceinline__ void cp16(uint32_t s, const void* g) {
    asm volatile("cp.async.cg.shared.global [%0], [%1], 16;" :: "r"(s), "l"(g));
}
__device__ __forceinline__ void cp_commit() {
    asm volatile("cp.async.commit_group;" ::: "memory");
}

#define LDM4(d, addr) \
    asm volatile("ldmatrix.sync.aligned.m8n8.x4.shared.b16 {%0,%1,%2,%3}, [%4];" \
                 : "=r"((d)[0]), "=r"((d)[1]), "=r"((d)[2]), "=r"((d)[3]) : "r"(addr))

#define MMA16816(d, a, b0v, b1v) \
    asm volatile("mma.sync.aligned.m16n8k16.row.col.f32.f16.f16.f32 " \
                 "{%0,%1,%2,%3}, {%4,%5,%6,%7}, {%8,%9}, {%0,%1,%2,%3};" \
                 : "+f"((d)[0]), "+f"((d)[1]), "+f"((d)[2]), "+f"((d)[3]) \
                 : "r"((a)[0]), "r"((a)[1]), "r"((a)[2]), "r"((a)[3]), \
                   "r"(b0v), "r"(b1v))

// ---------------------------------------------------------------------------
// Conversion kernels
// ---------------------------------------------------------------------------
// adapter [A,B,S,H] fp32 -> permuted rows m=bs*4+a, fp16
__global__ __launch_bounds__(256) void conv_x(const float* __restrict__ ad)
{
    const int m = blockIdx.x;
    const int a = m & 3;
    const int bs = m >> 2;
    const float* src = ad + ((size_t)((a * B_ + (bs >> 11)) * S_) + (bs & (S_ - 1))) * H_;
    const float4 v = ((const float4*)src)[threadIdx.x];
    __half2* ph = (__half2*)&g_xh[(size_t)m * H_ + threadIdx.x * 4];
    ph[0] = __floats2half2_rn(v.x, v.y);
    ph[1] = __floats2half2_rn(v.z, v.w);
}

// W [k,n] fp32 -> W^T [n,k] fp16; blockIdx.z selects matrix
__global__ __launch_bounds__(256) void conv_w(const float* __restrict__ Wq,
                                              const float* __restrict__ Wk,
                                              const float* __restrict__ Wv,
                                              const float* __restrict__ Wo)
{
    const int z = blockIdx.z;
    const float* W = (z == 0) ? Wq : (z == 1) ? Wk : (z == 2) ? Wv : Wo;
    __half* oh = g_wTh[z];
    __shared__ float tl[32][33];
    const int tx = threadIdx.x, ty = threadIdx.y;
    const int n0 = blockIdx.x * 32, k0 = blockIdx.y * 32;
#pragma unroll
    for (int i = 0; i < 4; i++)
        tl[ty + 8 * i][tx] = W[(size_t)(k0 + ty + 8 * i) * H_ + n0 + tx];
    __syncthreads();
#pragma unroll
    for (int i = 0; i < 4; i++)
        oh[(size_t)(n0 + ty + 8 * i) * H_ + k0 + tx] = __float2half_rn(tl[tx][ty + 8 * i]);
}

// ---------------------------------------------------------------------------
// fp16 single-pass GEMM: C[m,n] = A[m,:] . WT[n,:] + bias (+ resid)
// CTA 128x128, BK=64, 4-stage cp.async pipeline, 8 warps (2x4),
// warp tile 64x32, m16n8k16 HMMA fp32 accum.
// ---------------------------------------------------------------------------
#define A_OFF 0
#define B_OFF 16384
#define STAGE_B 32768
#define NSTAGE 4
#define DSMEM_B (NSTAGE * STAGE_B + 1024)

// SW128 swizzled offset of (row, 16B-chunk) within a 128-row x 128B tile
__device__ __forceinline__ uint32_t swoff(int r, int c16) {
    return (uint32_t)(r * 128 + ((c16 ^ (r & 7)) << 4));
}

__device__ __forceinline__ void load_chunk(uint32_t sb,
                                           const __half* __restrict__ Ah,
                                           const __half* __restrict__ Bh,
                                           int t, int mt, int nt, int c)
{
    const int kof = c * 64;
#pragma unroll
    for (int i = 0; i < 4; i++) {
        const int seg = t + i * 256;          // 0..1023
        const int r = seg >> 3, c16 = seg & 7;
        const uint32_t sw = swoff(r, c16);
        cp16(sb + A_OFF + sw, Ah + (size_t)(mt * 128 + r) * H_ + kof + c16 * 8);
        cp16(sb + B_OFF + sw, Bh + (size_t)(nt * 128 + r) * H_ + kof + c16 * 8);
    }
}

template <int MODE>
__global__ __launch_bounds__(256, 1)
void gemm_mma(const float* __restrict__ b0p, const float* __restrict__ b1p,
              const float* __restrict__ b2p, const float* __restrict__ resid)
{
    extern __shared__ __align__(1024) char dsm[];
    const uint32_t sbase = (smem_u32(dsm) + 1023) & ~1023u;

    const int t  = threadIdx.x;
    const int nt = blockIdx.x;
    const int mt = blockIdx.y;
    const int z  = (MODE == 0) ? blockIdx.z : 3;

    const __half* Ah = (MODE == 0) ? g_xh : g_ph;
    const __half* Bh = g_wTh[z];
    float* C = (MODE == 1) ? g_fused : (z == 0) ? g_Q : (z == 1) ? g_K : g_V;
    const float* bias = (MODE == 1) ? b0p : (z == 0) ? b0p : (z == 1) ? b1p : b2p;

    const int lane = t & 31;
    const int w  = t >> 5;
    const int wm = w >> 2;      // 0..1
    const int wn = w & 3;       // 0..3

    // ldmatrix per-lane bases
    const int xorv = lane & 7;
    const uint32_t aOff = (uint32_t)((wm * 64 + ((lane >> 3) & 1) * 8 + (lane & 7)) * 128);
    const int aCk = lane >> 4;           // k-chunk half
    const uint32_t bOff = (uint32_t)((wn * 32 + ((lane >> 4) << 3) + (lane & 7)) * 128);
    const int bCk = (lane >> 3) & 1;     // k-chunk half

    float acc[4][4][4];
#pragma unroll
    for (int mi = 0; mi < 4; mi++)
#pragma unroll
        for (int ni = 0; ni < 4; ni++)
#pragma unroll
            for (int r = 0; r < 4; r++) acc[mi][ni][r] = 0.0f;

    // prologue: stages 0..2
#pragma unroll
    for (int p = 0; p < NSTAGE - 1; p++) {
        load_chunk(sbase + p * STAGE_B, Ah, Bh, t, mt, nt, p);
        cp_commit();
    }

    const int NC = H_ / 64;   // 16
    for (int c = 0; c < NC; c++) {
        asm volatile("cp.async.wait_group %0;" :: "n"(NSTAGE - 2) : "memory");
        __syncthreads();
        // refill: buffer (c+3)&3 == (c-1)&3 was consumed at iter c-1;
        // the syncthreads above guarantees all warps are past it.
        if (c + NSTAGE - 1 < NC)
            load_chunk(sbase + ((c + NSTAGE - 1) & (NSTAGE - 1)) * STAGE_B,
                       Ah, Bh, t, mt, nt, c + NSTAGE - 1);
        cp_commit();   // unconditional: keeps wait_group(N-2) meaning "stage c done"

        const uint32_t sb = sbase + (c & (NSTAGE - 1)) * STAGE_B;
#pragma unroll
        for (int ks = 0; ks < 4; ks++) {
            uint32_t ah[4][4], bh[4][2];
            const uint32_t xa = (uint32_t)(((ks * 2 + aCk) ^ xorv) << 4);
            const uint32_t xb = (uint32_t)(((ks * 2 + bCk) ^ xorv) << 4);
#pragma unroll
            for (int mi = 0; mi < 4; mi++)
                LDM4(ah[mi], sb + A_OFF + aOff + mi * 2048 + xa);
#pragma unroll
            for (int pi = 0; pi < 2; pi++) {
                uint32_t tmp[4];
                LDM4(tmp, sb + B_OFF + bOff + pi * 2048 + xb);
                bh[2 * pi][0] = tmp[0]; bh[2 * pi][1] = tmp[1];
                bh[2 * pi + 1][0] = tmp[2]; bh[2 * pi + 1][1] = tmp[3];
            }
#pragma unroll
            for (int mi = 0; mi < 4; mi++)
#pragma unroll
                for (int ni = 0; ni < 4; ni++)
                    MMA16816(acc[mi][ni], ah[mi], bh[ni][0], bh[ni][1]);
        }
    }

    // Epilogue: bias (+ residual)
#pragma unroll
    for (int mi = 0; mi < 4; mi++) {
        const int r0 = mt * 128 + wm * 64 + mi * 16 + (lane >> 2);
        const int r1 = r0 + 8;
#pragma unroll
        for (int ni = 0; ni < 4; ni++) {
            const int col = nt * 128 + wn * 32 + ni * 8 + (lane & 3) * 2;
            const float2 bb = *(const float2*)(bias + col);
            float2 v01, v23;
            v01.x = acc[mi][ni][0] + bb.x; v01.y = acc[mi][ni][1] + bb.y;
            v23.x = acc[mi][ni][2] + bb.x; v23.y = acc[mi][ni][3] + bb.y;
            if (MODE == 1) {
                const float2 ra = *(const float2*)(resid + (size_t)r0 * H_ + col);
                const float2 rb = *(const float2*)(resid + (size_t)r1 * H_ + col);
                v01.x += ra.x; v01.y += ra.y;
                v23.x += rb.x; v23.y += rb.y;
            }
            *(float2*)(C + (size_t)r0 * H_ + col) = v01;
            *(float2*)(C + (size_t)r1 * H_ + col) = v23;
        }
    }
}

// ---------------------------------------------------------------------------
// Attention over adapter axis + mean pool -> fp16 pooled for O-GEMM
// ---------------------------------------------------------------------------
__global__ __launch_bounds__(256)
void attn_pool_kernel()
{
    const int warp = threadIdx.x >> 5;
    const int lane = threadIdx.x & 31;
    const int unit = blockIdx.x * 8 + warp;
    const int bs = unit >> 4;
    const int h  = unit & 15;

    const size_t base = (size_t)(bs * A_) * H_ + h * HD_;
    float q[A_][2], k[A_][2], v[A_][2];
#pragma unroll
    for (int a = 0; a < A_; a++) {
        const float* qp = g_Q + base + a * H_;
        const float* kp = g_K + base + a * H_;
        const float* vp = g_V + base + a * H_;
        q[a][0] = qp[lane]; q[a][1] = qp[lane + 32];
        k[a][0] = kp[lane]; k[a][1] = kp[lane + 32];
        v[a][0] = vp[lane]; v[a][1] = vp[lane + 32];
    }

    float sc[A_][A_];
#pragma unroll
    for (int i = 0; i < A_; i++)
#pragma unroll
        for (int j = 0; j < A_; j++)
            sc[i][j] = q[i][0] * k[j][0] + q[i][1] * k[j][1];

#pragma unroll
    for (int off = 16; off > 0; off >>= 1)
#pragma unroll
        for (int i = 0; i < A_; i++)
#pragma unroll
            for (int j = 0; j < A_; j++)
                sc[i][j] += __shfl_xor_sync(0xffffffffu, sc[i][j], off);

    float colw[A_] = {0.f, 0.f, 0.f, 0.f};
#pragma unroll
    for (int i = 0; i < A_; i++) {
        float s0 = sc[i][0] * 0.125f, s1 = sc[i][1] * 0.125f;
        float s2 = sc[i][2] * 0.125f, s3 = sc[i][3] * 0.125f;
        const float mx = fmaxf(fmaxf(s0, s1), fmaxf(s2, s3));
        const float e0 = __expf(s0 - mx), e1 = __expf(s1 - mx);
        const float e2 = __expf(s2 - mx), e3 = __expf(s3 - mx);
        const float inv = 1.0f / (e0 + e1 + e2 + e3);
        colw[0] += e0 * inv; colw[1] += e1 * inv;
        colw[2] += e2 * inv; colw[3] += e3 * inv;
    }

    float o0 = 0.f, o1 = 0.f;
#pragma unroll
    for (int j = 0; j < A_; j++) {
        const float c = colw[j] * 0.25f;
        o0 = fmaf(c, v[j][0], o0);
        o1 = fmaf(c, v[j][1], o1);
    }
    const size_t op = (size_t)bs * H_ + h * HD_;
    g_ph[op + lane]      = __float2half_rn(o0);
    g_ph[op + lane + 32] = __float2half_rn(o1);
}

// ---------------------------------------------------------------------------
// LayerNorm over H=1024 per row
// ---------------------------------------------------------------------------
__global__ __launch_bounds__(256)
void ln_kernel(const float* __restrict__ gamma,
               const float* __restrict__ beta,
               float* __restrict__ out)
{
    const int row = blockIdx.x;
    const int t = threadIdx.x;

    const float4 x = ((const float4*)(g_fused + (size_t)row * H_))[t];
    float s  = x.x + x.y + x.z + x.w;
    float ss = x.x * x.x + x.y * x.y + x.z * x.z + x.w * x.w;
#pragma unroll
    for (int off = 16; off > 0; off >>= 1) {
        s  += __shfl_xor_sync(0xffffffffu, s,  off);
        ss += __shfl_xor_sync(0xffffffffu, ss, off);
    }
    __shared__ float sh_s[8], sh_ss[8];
    if ((t & 31) == 0) { sh_s[t >> 5] = s; sh_ss[t >> 5] = ss; }
    __syncthreads();
    float tot = 0.f, tot2 = 0.f;
#pragma unroll
    for (int w = 0; w < 8; w++) { tot += sh_s[w]; tot2 += sh_ss[w]; }

    const float mu   = tot * (1.0f / H_);
    const float var  = tot2 * (1.0f / H_) - mu * mu;
    const float rstd = rsqrtf(var + 1e-5f);

    const float4 g = ((const float4*)gamma)[t];
    const float4 b = ((const float4*)beta)[t];
    float4 y;
    y.x = (x.x - mu) * rstd * g.x + b.x;
    y.y = (x.y - mu) * rstd * g.y + b.y;
    y.z = (x.z - mu) * rstd * g.z + b.z;
    y.w = (x.w - mu) * rstd * g.w + b.w;
    ((float4*)(out + (size_t)row * H_))[t] = y;
}

// ---------------------------------------------------------------------------
// Launch
// ---------------------------------------------------------------------------
extern "C" void kernel_launch(void* const* d_in, const int* in_sizes, int n_in,
                              void* d_out, int out_size)
{
    (void)in_sizes; (void)n_in; (void)out_size;
    const float* adapter = (const float*)d_in[0];
    const float* Wq = (const float*)d_in[1];
    const float* bq = (const float*)d_in[2];
    const float* Wk = (const float*)d_in[3];
    const float* bk = (const float*)d_in[4];
    const float* Wv = (const float*)d_in[5];
    const float* bv = (const float*)d_in[6];
    const float* Wo = (const float*)d_in[7];
    const float* bo = (const float*)d_in[8];
    const float* gamma = (const float*)d_in[9];
    const float* beta  = (const float*)d_in[10];
    float* out = (float*)d_out;

    cudaFuncSetAttribute(gemm_mma<0>, cudaFuncAttributeMaxDynamicSharedMemorySize, DSMEM_B);
    cudaFuncSetAttribute(gemm_mma<1>, cudaFuncAttributeMaxDynamicSharedMemorySize, DSMEM_B);

    conv_x<<<M1_, 256>>>(adapter);
    conv_w<<<dim3(32, 32, 4), dim3(32, 8)>>>(Wq, Wk, Wv, Wo);

    const dim3 gq(H_ / 128, M1_ / 128, 3);   // (8, 256, 3)
    gemm_mma<0><<<gq, 256, DSMEM_B>>>(bq, bk, bv, nullptr);

    attn_pool_kernel<<<(BS_ * NH_) / 8, 256>>>();

    const dim3 go(H_ / 128, BS_ / 128, 1);   // (8, 64)
    gemm_mma<1><<<go, 256, DSMEM_B>>>(bo, nullptr, nullptr, adapter);

    ln_kernel<<<BS_, 256>>>(gamma, beta, out);
}

// round 7
// speedup vs baseline: 6.2780x; 1.0937x over previous
#include <cuda_runtime.h>
#include <cuda_fp16.h>
#include <cstdint>

#define A_  4
#define B_  4
#define S_  2048
#define H_  1024
#define NH_ 16
#define HD_ 64
#define BS_ (B_ * S_)     // 8192
#define M1_ (BS_ * A_)    // 32768

// ---------------------------------------------------------------------------
// Scratch (device globals)
// ---------------------------------------------------------------------------
__device__ __align__(256) __half g_xh[M1_ * H_];        // 64 MB  (permuted x, fp16)
__device__ __align__(256) __half g_wTh[4][H_ * H_];     // 8 MB   (W^T [n][k], fp16)
__device__ __align__(256) __half g_ph[BS_ * H_];        // 16 MB  (pooled, fp16)
__device__ __align__(256) float g_fused[BS_ * H_];      // 32 MB

// ---------------------------------------------------------------------------
// PTX helpers (sm_80+ legal; no tcgen05 — base target rejects it)
// ---------------------------------------------------------------------------
__device__ __forceinline__ uint32_t smem_u32(const void* p) {
    uint32_t a;
    asm("{ .reg .u64 t; cvta.to.shared.u64 t, %1; cvt.u32.u64 %0, t; }" : "=r"(a) : "l"(p));
    return a;
}
__device__ __forceinline__ void cp16(uint32_t s, const void* g) {
    asm volatile("cp.async.cg.shared.global [%0], [%1], 16;" :: "r"(s), "l"(g));
}
__device__ __forceinline__ void cp_commit() {
    asm volatile("cp.async.commit_group;" ::: "memory");
}

#define LDM4(d, addr) \
    asm volatile("ldmatrix.sync.aligned.m8n8.x4.shared.b16 {%0,%1,%2,%3}, [%4];" \
                 : "=r"((d)[0]), "=r"((d)[1]), "=r"((d)[2]), "=r"((d)[3]) : "r"(addr))

#define MMA16816(d, a, b0v, b1v) \
    asm volatile("mma.sync.aligned.m16n8k16.row.col.f32.f16.f16.f32 " \
                 "{%0,%1,%2,%3}, {%4,%5,%6,%7}, {%8,%9}, {%0,%1,%2,%3};" \
                 : "+f"((d)[0]), "+f"((d)[1]), "+f"((d)[2]), "+f"((d)[3]) \
                 : "r"((a)[0]), "r"((a)[1]), "r"((a)[2]), "r"((a)[3]), \
                   "r"(b0v), "r"(b1v))

// SW128 swizzled offset of (row, 16B-chunk) within a 128B-row tile
__device__ __forceinline__ uint32_t swoff(int r, int c16) {
    return (uint32_t)(r * 128 + ((c16 ^ (r & 7)) << 4));
}

// ---------------------------------------------------------------------------
// Conversion kernels
// ---------------------------------------------------------------------------
__global__ __launch_bounds__(256) void conv_x(const float* __restrict__ ad)
{
    const int m = blockIdx.x;
    const int a = m & 3;
    const int bs = m >> 2;
    const float* src = ad + ((size_t)((a * B_ + (bs >> 11)) * S_) + (bs & (S_ - 1))) * H_;
    const float4 v = ((const float4*)src)[threadIdx.x];
    __half2* ph = (__half2*)&g_xh[(size_t)m * H_ + threadIdx.x * 4];
    ph[0] = __floats2half2_rn(v.x, v.y);
    ph[1] = __floats2half2_rn(v.z, v.w);
}

__global__ __launch_bounds__(256) void conv_w(const float* __restrict__ Wq,
                                              const float* __restrict__ Wk,
                                              const float* __restrict__ Wv,
                                              const float* __restrict__ Wo)
{
    const int z = blockIdx.z;
    const float* W = (z == 0) ? Wq : (z == 1) ? Wk : (z == 2) ? Wv : Wo;
    __half* oh = g_wTh[z];
    __shared__ float tl[32][33];
    const int tx = threadIdx.x, ty = threadIdx.y;
    const int n0 = blockIdx.x * 32, k0 = blockIdx.y * 32;
#pragma unroll
    for (int i = 0; i < 4; i++)
        tl[ty + 8 * i][tx] = W[(size_t)(k0 + ty + 8 * i) * H_ + n0 + tx];
    __syncthreads();
#pragma unroll
    for (int i = 0; i < 4; i++)
        oh[(size_t)(n0 + ty + 8 * i) * H_ + k0 + tx] = __float2half_rn(tl[tx][ty + 8 * i]);
}

// ---------------------------------------------------------------------------
// Fused QKV GEMM + attention + mean-pool.
// CTA = (head h, 128-row m-block). N=64 (one head), three 128x64 fp32
// accumulators (Q,K,V) over K=1024, 4-stage cp.async pipeline.
// Epilogue: Q/K/V (+bias) -> smem; per-bs softmax colsum attention; pooled
// fp16 written straight to g_ph. Q/K/V never touch DRAM.
// ---------------------------------------------------------------------------
#define FA_OFF 0          // A tile: 128 x 64 fp16 = 16 KB
#define FB_OFF 16384      // 3 B tiles: 64 x 64 fp16 = 8 KB each
#define FSTAGE 40960      // 40 KB per stage
#define FNSTAGE 4
#define FDSMEM (FNSTAGE * FSTAGE + 1024)   // 164864; attn overlay (99 KB) reuses it
#define QS_STRIDE 66      // padded fp32 row stride for attn smem

__device__ __forceinline__ void f_load_chunk(uint32_t sb, int t, int mt, int h, int c)
{
    const int kof = c * 64;
#pragma unroll
    for (int i = 0; i < 4; i++) {                 // A: 1024 segs
        const int seg = t + i * 256;
        const int r = seg >> 3, c16 = seg & 7;
        cp16(sb + FA_OFF + swoff(r, c16),
             g_xh + (size_t)(mt * 128 + r) * H_ + kof + c16 * 8);
    }
#pragma unroll
    for (int z = 0; z < 3; z++)
#pragma unroll
        for (int i = 0; i < 2; i++) {             // B: 512 segs per matrix
            const int seg = t + i * 256;
            const int r = seg >> 3, c16 = seg & 7;
            cp16(sb + FB_OFF + z * 8192 + swoff(r, c16),
                 g_wTh[z] + (size_t)(h * 64 + r) * H_ + kof + c16 * 8);
        }
}

__global__ __launch_bounds__(256, 1)
void fused_qkv_attn(const float* __restrict__ bq, const float* __restrict__ bk,
                    const float* __restrict__ bv)
{
    extern __shared__ __align__(1024) char dsm[];
    const uint32_t sbase = (smem_u32(dsm) + 1023) & ~1023u;
    float* qsm = (float*)(dsm + ((1024 - (smem_u32(dsm) & 1023)) & 1023));
    // qsm aliases sbase; three matrices of 128 x QS_STRIDE floats
    float* ksm = qsm + 128 * QS_STRIDE;
    float* vsm = ksm + 128 * QS_STRIDE;

    const int t  = threadIdx.x;
    const int h  = blockIdx.x;    // head
    const int mt = blockIdx.y;    // 128-row block

    const int lane = t & 31;
    const int w  = t >> 5;
    const int wm = w >> 1;        // 0..3  (32 rows each)
    const int wn = w & 1;         // 0..1  (32 cols each)

    const int xorv = lane & 7;
    const uint32_t aOff = (uint32_t)((wm * 32 + ((lane >> 3) & 1) * 8 + (lane & 7)) * 128);
    const int aCk = lane >> 4;
    const uint32_t bOffBase = (uint32_t)((wn * 32 + ((lane >> 4) << 3) + (lane & 7)) * 128);
    const int bCk = (lane >> 3) & 1;

    float acc[3][2][4][4];        // [z][mi][ni][reg]
#pragma unroll
    for (int z = 0; z < 3; z++)
#pragma unroll
        for (int mi = 0; mi < 2; mi++)
#pragma unroll
            for (int ni = 0; ni < 4; ni++)
#pragma unroll
                for (int r = 0; r < 4; r++) acc[z][mi][ni][r] = 0.0f;

#pragma unroll
    for (int p = 0; p < FNSTAGE - 1; p++) {
        f_load_chunk(sbase + p * FSTAGE, t, mt, h, p);
        cp_commit();
    }

    const int NC = H_ / 64;   // 16
    for (int c = 0; c < NC; c++) {
        asm volatile("cp.async.wait_group %0;" :: "n"(FNSTAGE - 2) : "memory");
        __syncthreads();
        if (c + FNSTAGE - 1 < NC)
            f_load_chunk(sbase + ((c + FNSTAGE - 1) & (FNSTAGE - 1)) * FSTAGE,
                         t, mt, h, c + FNSTAGE - 1);
        cp_commit();

        const uint32_t sb = sbase + (c & (FNSTAGE - 1)) * FSTAGE;
#pragma unroll
        for (int ks = 0; ks < 4; ks++) {
            const uint32_t xa = (uint32_t)(((ks * 2 + aCk) ^ xorv) << 4);
            const uint32_t xb = (uint32_t)(((ks * 2 + bCk) ^ xorv) << 4);
            uint32_t ah[2][4];
#pragma unroll
            for (int mi = 0; mi < 2; mi++)
                LDM4(ah[mi], sb + FA_OFF + aOff + mi * 2048 + xa);
            uint32_t bh[3][4][2];
#pragma unroll
            for (int z = 0; z < 3; z++)
#pragma unroll
                for (int pi = 0; pi < 2; pi++) {
                    uint32_t tmp[4];
                    LDM4(tmp, sb + FB_OFF + z * 8192 + bOffBase + pi * 2048 + xb);
                    bh[z][2 * pi][0] = tmp[0]; bh[z][2 * pi][1] = tmp[1];
                    bh[z][2 * pi + 1][0] = tmp[2]; bh[z][2 * pi + 1][1] = tmp[3];
                }
#pragma unroll
            for (int z = 0; z < 3; z++)
#pragma unroll
                for (int mi = 0; mi < 2; mi++)
#pragma unroll
                    for (int ni = 0; ni < 4; ni++)
                        MMA16816(acc[z][mi][ni], ah[mi], bh[z][ni][0], bh[z][ni][1]);
        }
    }
    __syncthreads();   // all warps done with pipeline smem before overlay

    // Epilogue 1: accumulators (+bias) -> smem
    const float* biasp[3] = {bq, bk, bv};
#pragma unroll
    for (int z = 0; z < 3; z++) {
        float* dst = (z == 0) ? qsm : (z == 1) ? ksm : vsm;
#pragma unroll
        for (int mi = 0; mi < 2; mi++) {
            const int r0 = wm * 32 + mi * 16 + (lane >> 2);
#pragma unroll
            for (int ni = 0; ni < 4; ni++) {
                const int col = wn * 32 + ni * 8 + (lane & 3) * 2;
                const float2 bb = *(const float2*)(biasp[z] + h * 64 + col);
                float2 v01, v23;
                v01.x = acc[z][mi][ni][0] + bb.x; v01.y = acc[z][mi][ni][1] + bb.y;
                v23.x = acc[z][mi][ni][2] + bb.x; v23.y = acc[z][mi][ni][3] + bb.y;
                *(float2*)(dst + r0 * QS_STRIDE + col) = v01;
                *(float2*)(dst + (r0 + 8) * QS_STRIDE + col) = v23;
            }
        }
    }
    __syncthreads();

    // Epilogue 2: attention over adapter axis + mean pool (warp per bs, 4 each)
#pragma unroll
    for (int g = 0; g < 4; g++) {
        const int lb = w * 4 + g;          // local bs 0..31
        float q[A_][2], k[A_][2], v[A_][2];
#pragma unroll
        for (int a = 0; a < A_; a++) {
            const int row = lb * 4 + a;
            q[a][0] = qsm[row * QS_STRIDE + lane];
            q[a][1] = qsm[row * QS_STRIDE + lane + 32];
            k[a][0] = ksm[row * QS_STRIDE + lane];
            k[a][1] = ksm[row * QS_STRIDE + lane + 32];
            v[a][0] = vsm[row * QS_STRIDE + lane];
            v[a][1] = vsm[row * QS_STRIDE + lane + 32];
        }
        float sc[A_][A_];
#pragma unroll
        for (int i = 0; i < A_; i++)
#pragma unroll
            for (int j = 0; j < A_; j++)
                sc[i][j] = q[i][0] * k[j][0] + q[i][1] * k[j][1];
#pragma unroll
        for (int off = 16; off > 0; off >>= 1)
#pragma unroll
            for (int i = 0; i < A_; i++)
#pragma unroll
                for (int j = 0; j < A_; j++)
                    sc[i][j] += __shfl_xor_sync(0xffffffffu, sc[i][j], off);

        float colw[A_] = {0.f, 0.f, 0.f, 0.f};
#pragma unroll
        for (int i = 0; i < A_; i++) {
            float s0 = sc[i][0] * 0.125f, s1 = sc[i][1] * 0.125f;
            float s2 = sc[i][2] * 0.125f, s3 = sc[i][3] * 0.125f;
            const float mx = fmaxf(fmaxf(s0, s1), fmaxf(s2, s3));
            const float e0 = __expf(s0 - mx), e1 = __expf(s1 - mx);
            const float e2 = __expf(s2 - mx), e3 = __expf(s3 - mx);
            const float inv = 1.0f / (e0 + e1 + e2 + e3);
            colw[0] += e0 * inv; colw[1] += e1 * inv;
            colw[2] += e2 * inv; colw[3] += e3 * inv;
        }
        float o0 = 0.f, o1 = 0.f;
#pragma unroll
        for (int j = 0; j < A_; j++) {
            const float cc = colw[j] * 0.25f;
            o0 = fmaf(cc, v[j][0], o0);
            o1 = fmaf(cc, v[j][1], o1);
        }
        const int bs = mt * 32 + lb;
        __half* op = g_ph + (size_t)bs * H_ + h * 64;
        op[lane]      = __float2half_rn(o0);
        op[lane + 32] = __float2half_rn(o1);
    }
}

// ---------------------------------------------------------------------------
// O-projection GEMM: g_fused = g_ph . WoT + bo + resid (adapter[0])
// CTA 128x128, BK=64, 4-stage pipeline (identical structure to R6 MODE 1).
// ---------------------------------------------------------------------------
#define A_OFF 0
#define B_OFF 16384
#define STAGE_B 32768
#define NSTAGE 4
#define DSMEM_B (NSTAGE * STAGE_B + 1024)

__device__ __forceinline__ void o_load_chunk(uint32_t sb, int t, int mt, int nt, int c)
{
    const int kof = c * 64;
#pragma unroll
    for (int i = 0; i < 4; i++) {
        const int seg = t + i * 256;
        const int r = seg >> 3, c16 = seg & 7;
        const uint32_t sw = swoff(r, c16);
        cp16(sb + A_OFF + sw, g_ph + (size_t)(mt * 128 + r) * H_ + kof + c16 * 8);
        cp16(sb + B_OFF + sw, g_wTh[3] + (size_t)(nt * 128 + r) * H_ + kof + c16 * 8);
    }
}

__global__ __launch_bounds__(256, 1)
void gemm_o(const float* __restrict__ bias, const float* __restrict__ resid)
{
    extern __shared__ __align__(1024) char dsm[];
    const uint32_t sbase = (smem_u32(dsm) + 1023) & ~1023u;

    const int t  = threadIdx.x;
    const int nt = blockIdx.x;
    const int mt = blockIdx.y;

    const int lane = t & 31;
    const int w  = t >> 5;
    const int wm = w >> 2;
    const int wn = w & 3;

    const int xorv = lane & 7;
    const uint32_t aOff = (uint32_t)((wm * 64 + ((lane >> 3) & 1) * 8 + (lane & 7)) * 128);
    const int aCk = lane >> 4;
    const uint32_t bOff = (uint32_t)((wn * 32 + ((lane >> 4) << 3) + (lane & 7)) * 128);
    const int bCk = (lane >> 3) & 1;

    float acc[4][4][4];
#pragma unroll
    for (int mi = 0; mi < 4; mi++)
#pragma unroll
        for (int ni = 0; ni < 4; ni++)
#pragma unroll
            for (int r = 0; r < 4; r++) acc[mi][ni][r] = 0.0f;

#pragma unroll
    for (int p = 0; p < NSTAGE - 1; p++) {
        o_load_chunk(sbase + p * STAGE_B, t, mt, nt, p);
        cp_commit();
    }

    const int NC = H_ / 64;
    for (int c = 0; c < NC; c++) {
        asm volatile("cp.async.wait_group %0;" :: "n"(NSTAGE - 2) : "memory");
        __syncthreads();
        if (c + NSTAGE - 1 < NC)
            o_load_chunk(sbase + ((c + NSTAGE - 1) & (NSTAGE - 1)) * STAGE_B,
                         t, mt, nt, c + NSTAGE - 1);
        cp_commit();

        const uint32_t sb = sbase + (c & (NSTAGE - 1)) * STAGE_B;
#pragma unroll
        for (int ks = 0; ks < 4; ks++) {
            uint32_t ah[4][4], bh[4][2];
            const uint32_t xa = (uint32_t)(((ks * 2 + aCk) ^ xorv) << 4);
            const uint32_t xb = (uint32_t)(((ks * 2 + bCk) ^ xorv) << 4);
#pragma unroll
            for (int mi = 0; mi < 4; mi++)
                LDM4(ah[mi], sb + A_OFF + aOff + mi * 2048 + xa);
#pragma unroll
            for (int pi = 0; pi < 2; pi++) {
                uint32_t tmp[4];
                LDM4(tmp, sb + B_OFF + bOff + pi * 2048 + xb);
                bh[2 * pi][0] = tmp[0]; bh[2 * pi][1] = tmp[1];
                bh[2 * pi + 1][0] = tmp[2]; bh[2 * pi + 1][1] = tmp[3];
            }
#pragma unroll
            for (int mi = 0; mi < 4; mi++)
#pragma unroll
                for (int ni = 0; ni < 4; ni++)
                    MMA16816(acc[mi][ni], ah[mi], bh[ni][0], bh[ni][1]);
        }
    }

#pragma unroll
    for (int mi = 0; mi < 4; mi++) {
        const int r0 = mt * 128 + wm * 64 + mi * 16 + (lane >> 2);
        const int r1 = r0 + 8;
#pragma unroll
        for (int ni = 0; ni < 4; ni++) {
            const int col = nt * 128 + wn * 32 + ni * 8 + (lane & 3) * 2;
            const float2 bb = *(const float2*)(bias + col);
            const float2 ra = *(const float2*)(resid + (size_t)r0 * H_ + col);
            const float2 rb = *(const float2*)(resid + (size_t)r1 * H_ + col);
            float2 v01, v23;
            v01.x = acc[mi][ni][0] + bb.x + ra.x; v01.y = acc[mi][ni][1] + bb.y + ra.y;
            v23.x = acc[mi][ni][2] + bb.x + rb.x; v23.y = acc[mi][ni][3] + bb.y + rb.y;
            *(float2*)(g_fused + (size_t)r0 * H_ + col) = v01;
            *(float2*)(g_fused + (size_t)r1 * H_ + col) = v23;
        }
    }
}

// ---------------------------------------------------------------------------
// LayerNorm over H=1024 per row
// ---------------------------------------------------------------------------
__global__ __launch_bounds__(256)
void ln_kernel(const float* __restrict__ gamma,
               const float* __restrict__ beta,
               float* __restrict__ out)
{
    const int row = blockIdx.x;
    const int t = threadIdx.x;

    const float4 x = ((const float4*)(g_fused + (size_t)row * H_))[t];
    float s  = x.x + x.y + x.z + x.w;
    float ss = x.x * x.x + x.y * x.y + x.z * x.z + x.w * x.w;
#pragma unroll
    for (int off = 16; off > 0; off >>= 1) {
        s  += __shfl_xor_sync(0xffffffffu, s,  off);
        ss += __shfl_xor_sync(0xffffffffu, ss, off);
    }
    __shared__ float sh_s[8], sh_ss[8];
    if ((t & 31) == 0) { sh_s[t >> 5] = s; sh_ss[t >> 5] = ss; }
    __syncthreads();
    float tot = 0.f, tot2 = 0.f;
#pragma unroll
    for (int w = 0; w < 8; w++) { tot += sh_s[w]; tot2 += sh_ss[w]; }

    const float mu   = tot * (1.0f / H_);
    const float var  = tot2 * (1.0f / H_) - mu * mu;
    const float rstd = rsqrtf(var + 1e-5f);

    const float4 g = ((const float4*)gamma)[t];
    const float4 b = ((const float4*)beta)[t];
    float4 y;
    y.x = (x.x - mu) * rstd * g.x + b.x;
    y.y = (x.y - mu) * rstd * g.y + b.y;
    y.z = (x.z - mu) * rstd * g.z + b.z;
    y.w = (x.w - mu) * rstd * g.w + b.w;
    ((float4*)(out + (size_t)row * H_))[t] = y;
}

// ---------------------------------------------------------------------------
// Launch
// ---------------------------------------------------------------------------
extern "C" void kernel_launch(void* const* d_in, const int* in_sizes, int n_in,
                              void* d_out, int out_size)
{
    (void)in_sizes; (void)n_in; (void)out_size;
    const float* adapter = (const float*)d_in[0];
    const float* Wq = (const float*)d_in[1];
    const float* bq = (const float*)d_in[2];
    const float* Wk = (const float*)d_in[3];
    const float* bk = (const float*)d_in[4];
    const float* Wv = (const float*)d_in[5];
    const float* bv = (const float*)d_in[6];
    const float* Wo = (const float*)d_in[7];
    const float* bo = (const float*)d_in[8];
    const float* gamma = (const float*)d_in[9];
    const float* beta  = (const float*)d_in[10];
    float* out = (float*)d_out;

    cudaFuncSetAttribute(fused_qkv_attn, cudaFuncAttributeMaxDynamicSharedMemorySize, FDSMEM);
    cudaFuncSetAttribute(gemm_o, cudaFuncAttributeMaxDynamicSharedMemorySize, DSMEM_B);

    conv_x<<<M1_, 256>>>(adapter);
    conv_w<<<dim3(32, 32, 4), dim3(32, 8)>>>(Wq, Wk, Wv, Wo);

    const dim3 gf(NH_, M1_ / 128);    // (16 heads, 256 m-blocks)
    fused_qkv_attn<<<gf, 256, FDSMEM>>>(bq, bk, bv);

    const dim3 go(H_ / 128, BS_ / 128);   // (8, 64)
    gemm_o<<<go, 256, DSMEM_B>>>(bo, adapter);

    ln_kernel<<<BS_, 256>>>(gamma, beta, out);
}